// round 5
// baseline (speedup 1.0000x reference)
#include <cuda_runtime.h>

// ---------------- problem constants ----------------
#define BB    4
#define NANCH 211200
#define CC    256
#define HH    200
#define WW    176
#define KK    4096

#define NBOX      (BB * NANCH)          // 844,800
#define BOX_ELEMS (NBOX * 7)            // 5,913,600

#define GATHER_BLOCKS (BB * CC)         // 1024, one per (b, c) plane
#define BOXES_PER_BLOCK 1024            // 4 boxes per thread
#define DECODE_BLOCKS (NBOX / BOXES_PER_BLOCK)  // 825 (exact)

#define PLANE_FLOATS (HH * WW)          // 35,200
#define SMEM_BYTES   (PLANE_FLOATS * 4) // 140,800

// ---------------- decode for one box ----------------
__device__ __forceinline__ void decode_one(const float* __restrict__ deltas,
                                           const float* __restrict__ anchors,
                                           float* __restrict__ out, int box)
{
    size_t base = (size_t)box * 7;
    float d0 = deltas[base + 0], d1 = deltas[base + 1], d2 = deltas[base + 2];
    float d3 = deltas[base + 3], d4 = deltas[base + 4], d5 = deltas[base + 5];
    float d6 = deltas[base + 6];
    float a0 = anchors[base + 0], a1 = anchors[base + 1], a2 = anchors[base + 2];
    float a3 = anchors[base + 3], a4 = anchors[base + 4], a5 = anchors[base + 5];
    float a6 = anchors[base + 6];

    float dnorm = sqrtf(a3 * a3 + a4 * a4);

    out[base + 0] = d0 * dnorm + a0;
    out[base + 1] = d1 * dnorm + a1;
    out[base + 2] = d2 * a5 + a2;
    out[base + 3] = expf(d3) * a3;
    out[base + 4] = expf(d4) * a4;
    out[base + 5] = expf(d5) * a5;
    out[base + 6] = d6 + a6;
}

// ---------------- fused kernel ----------------
// blocks [0, 1024)        : BEV gather, one (b,c) plane staged in smem
// blocks [1024, 1024+825) : box decode, 1024 boxes per block
__global__ void __launch_bounds__(256)
fused_kernel(const float* __restrict__ deltas,
             const float* __restrict__ anchors,
             const float* __restrict__ fm,
             const float* __restrict__ kp,
             float* __restrict__ boxes,
             float* __restrict__ bev)
{
    extern __shared__ float plane[];
    const int blk = blockIdx.x;

    if (blk < GATHER_BLOCKS) {
        const int b = blk >> 8;                 // blk / CC
        const float4* __restrict__ src =
            (const float4*)(fm + (size_t)blk * PLANE_FLOATS);
        float4* __restrict__ dst = (float4*)plane;

        // stage plane into smem: 8800 float4 / 256 threads = 34.375 iters.
        // Unroll in chunks of 8 for high MLP; handle the tail separately.
        {
            const int FULL = (PLANE_FLOATS / 4 / 256) & ~7;   // 32 iters
            int i = threadIdx.x;
            #pragma unroll 8
            for (int t = 0; t < FULL; t++, i += 256)
                dst[i] = src[i];
            for (; i < PLANE_FLOATS / 4; i += 256)
                dst[i] = src[i];
        }
        __syncthreads();

        const float* __restrict__ kpb  = kp  + (size_t)b * KK * 3;
        float*       __restrict__ orow = bev + (size_t)blk * KK;

        #pragma unroll 4
        for (int t = 0; t < KK / 256; t++) {
            int k = t * 256 + threadIdx.x;
            float x = __ldg(kpb + k * 3 + 0);
            float y = __ldg(kpb + k * 3 + 1);

            // --- coord transform (matches reference exactly) ---
            const float px = 0.05f * 8.0f;      // base_pixel_size * STRIDE
            float idx_x = x / px;
            float idx_y = (y + 40.0f) / px;
            idx_x = fminf(fmaxf(idx_x, 0.0f), (float)(WW - 1));
            idx_y = fminf(fmaxf(idx_y, 0.0f), (float)(HH - 1));
            float nx = 2.0f * (idx_x / (float)(WW - 2)) - 1.0f;
            float ny = 2.0f * (idx_y / (float)(HH - 2)) - 1.0f;
            // grid = flip(indices): width driven by ny, height by nx
            float ix = (ny + 1.0f) * 0.5f * (float)(WW - 1);
            float iy = (nx + 1.0f) * 0.5f * (float)(HH - 1);

            // --- bilinear from smem ---
            float x0f = floorf(ix);
            float y0f = floorf(iy);
            float wx = ix - x0f;
            float wy = iy - y0f;
            int x0 = (int)x0f, y0 = (int)y0f;
            int x1 = x0 + 1,   y1 = y0 + 1;

            float vx0 = (x0 >= 0 && x0 <= WW - 1) ? 1.0f : 0.0f;
            float vx1 = (x1 >= 0 && x1 <= WW - 1) ? 1.0f : 0.0f;
            float vy0 = (y0 >= 0 && y0 <= HH - 1) ? 1.0f : 0.0f;
            float vy1 = (y1 >= 0 && y1 <= HH - 1) ? 1.0f : 0.0f;

            int x0c = min(max(x0, 0), WW - 1);
            int x1c = min(max(x1, 0), WW - 1);
            int y0c = min(max(y0, 0), HH - 1);
            int y1c = min(max(y1, 0), HH - 1);

            float v00 = plane[y0c * WW + x0c];
            float v01 = plane[y0c * WW + x1c];
            float v10 = plane[y1c * WW + x0c];
            float v11 = plane[y1c * WW + x1c];

            float w00 = (1.0f - wx) * (1.0f - wy) * (vx0 * vy0);
            float w01 = wx          * (1.0f - wy) * (vx1 * vy0);
            float w10 = (1.0f - wx) * wy          * (vx0 * vy1);
            float w11 = wx          * wy          * (vx1 * vy1);

            orow[k] = v00 * w00 + v01 * w01 + v10 * w10 + v11 * w11;
        }
    } else {
        // ---------------- decode ----------------
        int base = (blk - GATHER_BLOCKS) * BOXES_PER_BLOCK + threadIdx.x;
        #pragma unroll
        for (int j = 0; j < BOXES_PER_BLOCK / 256; j++)
            decode_one(deltas, anchors, boxes, base + j * 256);
    }
}

// ---------------- launch ----------------
extern "C" void kernel_launch(void* const* d_in, const int* in_sizes, int n_in,
                              void* d_out, int out_size)
{
    const float* deltas  = (const float*)d_in[0];
    const float* anchors = (const float*)d_in[1];
    const float* fm      = (const float*)d_in[2];
    const float* kp      = (const float*)d_in[3];

    float* boxes_out = (float*)d_out;
    float* bev_out   = (float*)d_out + BOX_ELEMS;

    cudaFuncSetAttribute(fused_kernel,
                         cudaFuncAttributeMaxDynamicSharedMemorySize, SMEM_BYTES);

    fused_kernel<<<GATHER_BLOCKS + DECODE_BLOCKS, 256, SMEM_BYTES>>>(
        deltas, anchors, fm, kp, boxes_out, bev_out);

    (void)in_sizes; (void)n_in; (void)out_size;
}

// round 6
// speedup vs baseline: 1.9132x; 1.9132x over previous
#include <cuda_runtime.h>

// ---------------- problem constants ----------------
#define BB    4
#define NANCH 211200
#define CC    256
#define HH    200
#define WW    176
#define KK    4096

#define NBOX      (BB * NANCH)          // 844,800
#define BOX_ELEMS (NBOX * 7)            // 5,913,600

#define THREADS   1024

#define GATHER_BLOCKS (BB * CC)                 // 1024, one per (b, c) plane
#define DECODE_BLOCKS (NBOX / THREADS)          // 825 (exact)
#define TOTAL_BLOCKS  (GATHER_BLOCKS + DECODE_BLOCKS)  // 1849

#define PLANE_FLOATS (HH * WW)          // 35,200
#define SMEM_BYTES   (PLANE_FLOATS * 4) // 140,800

// ---------------- decode for one box ----------------
__device__ __forceinline__ void decode_one(const float* __restrict__ deltas,
                                           const float* __restrict__ anchors,
                                           float* __restrict__ out, int box)
{
    size_t base = (size_t)box * 7;
    float d0 = deltas[base + 0], d1 = deltas[base + 1], d2 = deltas[base + 2];
    float d3 = deltas[base + 3], d4 = deltas[base + 4], d5 = deltas[base + 5];
    float d6 = deltas[base + 6];
    float a0 = anchors[base + 0], a1 = anchors[base + 1], a2 = anchors[base + 2];
    float a3 = anchors[base + 3], a4 = anchors[base + 4], a5 = anchors[base + 5];
    float a6 = anchors[base + 6];

    float dnorm = sqrtf(a3 * a3 + a4 * a4);

    out[base + 0] = d0 * dnorm + a0;
    out[base + 1] = d1 * dnorm + a1;
    out[base + 2] = d2 * a5 + a2;
    out[base + 3] = expf(d3) * a3;
    out[base + 4] = expf(d4) * a4;
    out[base + 5] = expf(d5) * a5;
    out[base + 6] = d6 + a6;
}

// ---------------- gather for one (b,c) plane ----------------
__device__ __forceinline__ void gather_plane(int gblk,
                                             const float* __restrict__ fm,
                                             const float* __restrict__ kp,
                                             float* __restrict__ bev,
                                             float* __restrict__ plane)
{
    const int b = gblk >> 8;                    // gblk / CC
    const float4* __restrict__ src =
        (const float4*)(fm + (size_t)gblk * PLANE_FLOATS);
    float4* __restrict__ dst = (float4*)plane;

    // stage plane: 8800 float4 / 1024 threads = 8.59 iters
    {
        const int N4   = PLANE_FLOATS / 4;      // 8800
        const int FULL = (N4 / THREADS) & ~7;   // 8
        int i = threadIdx.x;
        #pragma unroll 8
        for (int t = 0; t < FULL; t++, i += THREADS)
            dst[i] = src[i];
        for (; i < N4; i += THREADS)
            dst[i] = src[i];
    }
    __syncthreads();

    const float* __restrict__ kpb  = kp  + (size_t)b * KK * 3;
    float*       __restrict__ orow = bev + (size_t)gblk * KK;

    #pragma unroll
    for (int t = 0; t < KK / THREADS; t++) {
        int k = t * THREADS + threadIdx.x;
        float x = __ldg(kpb + k * 3 + 0);
        float y = __ldg(kpb + k * 3 + 1);

        // --- coord transform (matches reference exactly) ---
        const float px = 0.05f * 8.0f;          // base_pixel_size * STRIDE
        float idx_x = x / px;
        float idx_y = (y + 40.0f) / px;
        idx_x = fminf(fmaxf(idx_x, 0.0f), (float)(WW - 1));
        idx_y = fminf(fmaxf(idx_y, 0.0f), (float)(HH - 1));
        float nx = 2.0f * (idx_x / (float)(WW - 2)) - 1.0f;
        float ny = 2.0f * (idx_y / (float)(HH - 2)) - 1.0f;
        // grid = flip(indices): width driven by ny, height by nx
        float ix = (ny + 1.0f) * 0.5f * (float)(WW - 1);
        float iy = (nx + 1.0f) * 0.5f * (float)(HH - 1);

        // --- bilinear from smem ---
        float x0f = floorf(ix);
        float y0f = floorf(iy);
        float wx = ix - x0f;
        float wy = iy - y0f;
        int x0 = (int)x0f, y0 = (int)y0f;
        int x1 = x0 + 1,   y1 = y0 + 1;

        float vx0 = (x0 >= 0 && x0 <= WW - 1) ? 1.0f : 0.0f;
        float vx1 = (x1 >= 0 && x1 <= WW - 1) ? 1.0f : 0.0f;
        float vy0 = (y0 >= 0 && y0 <= HH - 1) ? 1.0f : 0.0f;
        float vy1 = (y1 >= 0 && y1 <= HH - 1) ? 1.0f : 0.0f;

        int x0c = min(max(x0, 0), WW - 1);
        int x1c = min(max(x1, 0), WW - 1);
        int y0c = min(max(y0, 0), HH - 1);
        int y1c = min(max(y1, 0), HH - 1);

        float v00 = plane[y0c * WW + x0c];
        float v01 = plane[y0c * WW + x1c];
        float v10 = plane[y1c * WW + x0c];
        float v11 = plane[y1c * WW + x1c];

        float w00 = (1.0f - wx) * (1.0f - wy) * (vx0 * vy0);
        float w01 = wx          * (1.0f - wy) * (vx1 * vy0);
        float w10 = (1.0f - wx) * wy          * (vx0 * vy1);
        float w11 = wx          * wy          * (vx1 * vy1);

        orow[k] = v00 * w00 + v01 * w01 + v10 * w10 + v11 * w11;
    }
}

// ---------------- fused kernel ----------------
// Block roles are interleaved (even/odd) over the first 2*DECODE_BLOCKS
// indices so each scheduling wave mixes streaming decode with smem gather,
// smoothing DRAM demand.
__global__ void __launch_bounds__(THREADS)
fused_kernel(const float* __restrict__ deltas,
             const float* __restrict__ anchors,
             const float* __restrict__ fm,
             const float* __restrict__ kp,
             float* __restrict__ boxes,
             float* __restrict__ bev)
{
    extern __shared__ float plane[];
    const int blk = blockIdx.x;

    int gather_idx = -1, decode_idx = -1;
    if (blk < 2 * DECODE_BLOCKS) {
        if (blk & 1) decode_idx = blk >> 1;
        else         gather_idx = blk >> 1;
    } else {
        gather_idx = blk - DECODE_BLOCKS;       // 825 .. 1023
    }

    if (gather_idx >= 0) {
        gather_plane(gather_idx, fm, kp, bev, plane);
    } else {
        int box = decode_idx * THREADS + threadIdx.x;
        decode_one(deltas, anchors, boxes, box);
    }
}

// ---------------- launch ----------------
extern "C" void kernel_launch(void* const* d_in, const int* in_sizes, int n_in,
                              void* d_out, int out_size)
{
    const float* deltas  = (const float*)d_in[0];
    const float* anchors = (const float*)d_in[1];
    const float* fm      = (const float*)d_in[2];
    const float* kp      = (const float*)d_in[3];

    float* boxes_out = (float*)d_out;
    float* bev_out   = (float*)d_out + BOX_ELEMS;

    cudaFuncSetAttribute(fused_kernel,
                         cudaFuncAttributeMaxDynamicSharedMemorySize, SMEM_BYTES);

    fused_kernel<<<TOTAL_BLOCKS, THREADS, SMEM_BYTES>>>(
        deltas, anchors, fm, kp, boxes_out, bev_out);

    (void)in_sizes; (void)n_in; (void)out_size;
}

// round 7
// speedup vs baseline: 1.9743x; 1.0320x over previous
#include <cuda_runtime.h>

// ---------------- problem constants ----------------
#define BB    4
#define NANCH 211200
#define CC    256
#define HH    200
#define WW    176
#define KK    4096

#define NBOX      (BB * NANCH)          // 844,800
#define BOX_ELEMS (NBOX * 7)            // 5,913,600

#define THREADS   1024

#define GATHER_BLOCKS (BB * CC)                 // 1024, one per (b, c) plane
#define DECODE_BLOCKS (NBOX / THREADS)          // 825 (exact)
#define TOTAL_BLOCKS  (GATHER_BLOCKS + DECODE_BLOCKS)  // 1849

#define PLANE_FLOATS (HH * WW)          // 35,200
#define SMEM_BYTES   (PLANE_FLOATS * 4) // 140,800

// Precomputed per-(b,k) sample data: 4 clamped corner offsets + 4 weights
// (validity folded into weights). 16384 entries, L2-resident, read 256x each.
__device__ ushort4 g_off[BB * KK];
__device__ float4  g_wgt[BB * KK];

// ---------------- kernel 1: per-keypoint precompute ----------------
__global__ void precompute_kernel(const float* __restrict__ kp)
{
    int i = blockIdx.x * blockDim.x + threadIdx.x;
    if (i >= BB * KK) return;

    float x = kp[i * 3 + 0];
    float y = kp[i * 3 + 1];

    // --- coord transform (matches reference exactly) ---
    const float px = 0.05f * 8.0f;              // base_pixel_size * STRIDE
    float idx_x = x / px;
    float idx_y = (y + 40.0f) / px;
    idx_x = fminf(fmaxf(idx_x, 0.0f), (float)(WW - 1));
    idx_y = fminf(fmaxf(idx_y, 0.0f), (float)(HH - 1));
    float nx = 2.0f * (idx_x / (float)(WW - 2)) - 1.0f;
    float ny = 2.0f * (idx_y / (float)(HH - 2)) - 1.0f;
    // grid = flip(indices): width driven by ny, height by nx
    float ix = (ny + 1.0f) * 0.5f * (float)(WW - 1);
    float iy = (nx + 1.0f) * 0.5f * (float)(HH - 1);

    float x0f = floorf(ix);
    float y0f = floorf(iy);
    float wx = ix - x0f;
    float wy = iy - y0f;
    int x0 = (int)x0f, y0 = (int)y0f;
    int x1 = x0 + 1,   y1 = y0 + 1;

    float vx0 = (x0 >= 0 && x0 <= WW - 1) ? 1.0f : 0.0f;
    float vx1 = (x1 >= 0 && x1 <= WW - 1) ? 1.0f : 0.0f;
    float vy0 = (y0 >= 0 && y0 <= HH - 1) ? 1.0f : 0.0f;
    float vy1 = (y1 >= 0 && y1 <= HH - 1) ? 1.0f : 0.0f;

    int x0c = min(max(x0, 0), WW - 1);
    int x1c = min(max(x1, 0), WW - 1);
    int y0c = min(max(y0, 0), HH - 1);
    int y1c = min(max(y1, 0), HH - 1);

    g_off[i] = make_ushort4((unsigned short)(y0c * WW + x0c),
                            (unsigned short)(y0c * WW + x1c),
                            (unsigned short)(y1c * WW + x0c),
                            (unsigned short)(y1c * WW + x1c));
    g_wgt[i] = make_float4((1.0f - wx) * (1.0f - wy) * (vx0 * vy0),
                           wx          * (1.0f - wy) * (vx1 * vy0),
                           (1.0f - wx) * wy          * (vx0 * vy1),
                           wx          * wy          * (vx1 * vy1));
}

// ---------------- decode for one box ----------------
__device__ __forceinline__ void decode_one(const float* __restrict__ deltas,
                                           const float* __restrict__ anchors,
                                           float* __restrict__ out, int box)
{
    size_t base = (size_t)box * 7;
    float d0 = deltas[base + 0], d1 = deltas[base + 1], d2 = deltas[base + 2];
    float d3 = deltas[base + 3], d4 = deltas[base + 4], d5 = deltas[base + 5];
    float d6 = deltas[base + 6];
    float a0 = anchors[base + 0], a1 = anchors[base + 1], a2 = anchors[base + 2];
    float a3 = anchors[base + 3], a4 = anchors[base + 4], a5 = anchors[base + 5];
    float a6 = anchors[base + 6];

    float dnorm = sqrtf(a3 * a3 + a4 * a4);

    out[base + 0] = d0 * dnorm + a0;
    out[base + 1] = d1 * dnorm + a1;
    out[base + 2] = d2 * a5 + a2;
    out[base + 3] = expf(d3) * a3;
    out[base + 4] = expf(d4) * a4;
    out[base + 5] = expf(d5) * a5;
    out[base + 6] = d6 + a6;
}

// ---------------- gather for one (b,c) plane ----------------
__device__ __forceinline__ void gather_plane(int gblk,
                                             const float* __restrict__ fm,
                                             float* __restrict__ bev,
                                             float* __restrict__ plane)
{
    const int b = gblk >> 8;                    // gblk / CC
    const float4* __restrict__ src =
        (const float4*)(fm + (size_t)gblk * PLANE_FLOATS);
    float4* __restrict__ dst = (float4*)plane;

    // stage plane: 8800 float4 / 1024 threads = 8.59 iters
    {
        const int N4   = PLANE_FLOATS / 4;      // 8800
        const int FULL = (N4 / THREADS) & ~7;   // 8
        int i = threadIdx.x;
        #pragma unroll 8
        for (int t = 0; t < FULL; t++, i += THREADS)
            dst[i] = src[i];
        for (; i < N4; i += THREADS)
            dst[i] = src[i];
    }
    __syncthreads();

    float* __restrict__ orow = bev + (size_t)gblk * KK;
    const int base = b * KK + threadIdx.x;

    // prefetch all 4 iterations' offsets & weights up-front for MLP
    ushort4 o[KK / THREADS];
    float4  w[KK / THREADS];
    #pragma unroll
    for (int t = 0; t < KK / THREADS; t++) {
        o[t] = __ldg(&g_off[base + t * THREADS]);
        w[t] = __ldg(&g_wgt[base + t * THREADS]);
    }

    #pragma unroll
    for (int t = 0; t < KK / THREADS; t++) {
        float r = plane[o[t].x] * w[t].x
                + plane[o[t].y] * w[t].y
                + plane[o[t].z] * w[t].z
                + plane[o[t].w] * w[t].w;
        orow[t * THREADS + threadIdx.x] = r;
    }
}

// ---------------- fused kernel ----------------
// Block roles interleaved (even/odd over first 2*DECODE_BLOCKS) so each
// scheduling wave mixes streaming decode with smem gather.
__global__ void __launch_bounds__(THREADS)
fused_kernel(const float* __restrict__ deltas,
             const float* __restrict__ anchors,
             const float* __restrict__ fm,
             float* __restrict__ boxes,
             float* __restrict__ bev)
{
    extern __shared__ float plane[];
    const int blk = blockIdx.x;

    int gather_idx = -1, decode_idx = -1;
    if (blk < 2 * DECODE_BLOCKS) {
        if (blk & 1) decode_idx = blk >> 1;
        else         gather_idx = blk >> 1;
    } else {
        gather_idx = blk - DECODE_BLOCKS;       // 825 .. 1023
    }

    if (gather_idx >= 0) {
        gather_plane(gather_idx, fm, bev, plane);
    } else {
        int box = decode_idx * THREADS + threadIdx.x;
        decode_one(deltas, anchors, boxes, box);
    }
}

// ---------------- launch ----------------
extern "C" void kernel_launch(void* const* d_in, const int* in_sizes, int n_in,
                              void* d_out, int out_size)
{
    const float* deltas  = (const float*)d_in[0];
    const float* anchors = (const float*)d_in[1];
    const float* fm      = (const float*)d_in[2];
    const float* kp      = (const float*)d_in[3];

    float* boxes_out = (float*)d_out;
    float* bev_out   = (float*)d_out + BOX_ELEMS;

    // 1. per-keypoint offsets + weights (tiny)
    precompute_kernel<<<(BB * KK + 255) / 256, 256>>>(kp);

    // 2. fused gather + decode
    cudaFuncSetAttribute(fused_kernel,
                         cudaFuncAttributeMaxDynamicSharedMemorySize, SMEM_BYTES);
    fused_kernel<<<TOTAL_BLOCKS, THREADS, SMEM_BYTES>>>(
        deltas, anchors, fm, boxes_out, bev_out);

    (void)in_sizes; (void)n_in; (void)out_size;
}